// round 8
// baseline (speedup 1.0000x reference)
#include <cuda_runtime.h>
#include <math.h>

#define B_    1024
#define C_    1024
#define E_    128
#define SPLIT 8
#define RPB   (C_ / SPLIT)    // 128 rows per fused block
#define WPB   4               // warps per fused block
#define RPW   (RPB / WPB)     // 32 rows per warp
#define NGRP  (RPW / 4)       // 8 groups of 4 rows

// ---------------- device scratch (allocation-free rule) ----------------
__device__ float g_u [B_ * 8 * E_];          // per-batch per-head score vectors (0.25 folded)
__device__ float g_qb[B_ * 8];               // per-head score bias (0.25 folded)
__device__ float g_pl[B_ * SPLIT * 8];       // partial sum-exp
__device__ float g_ps[(size_t)B_ * SPLIT * 8 * E_];  // partial weighted h sums
__device__ float g_w [B_ * E_];              // logits matvec vector
__device__ float g_kb[B_];                   // logits scalar bias

// ---------------- f32x2 helpers (sm_103 packed fp32) ----------------
__device__ __forceinline__ unsigned long long pk2(float x, float y) {
    unsigned long long r;
    asm("mov.b64 %0, {%1, %2};" : "=l"(r) : "f"(x), "f"(y));
    return r;
}
__device__ __forceinline__ float2 upk2(unsigned long long v) {
    float2 r;
    asm("mov.b64 {%0, %1}, %2;" : "=f"(r.x), "=f"(r.y) : "l"(v));
    return r;
}
#define MUL2(d, a, b) asm("mul.rn.f32x2 %0, %1, %2;" : "=l"(d) : "l"(a), "l"(b))
#define FMA2(d, a, b) asm("fma.rn.f32x2 %0, %1, %2, %0;" : "+l"(d) : "l"(a), "l"(b))

// ---------------------------------------------------------------------------
// K0: per batch — q = Qw@hc + Qb;  u[h][:] = 0.25 * q_h^T Vw_h ;  qb[h] = 0.25 q_h.Vb_h
// ---------------------------------------------------------------------------
__global__ void __launch_bounds__(128) k_prep(
    const float* __restrict__ hN, const float* __restrict__ hpr,
    const float* __restrict__ h0,
    const float* __restrict__ Qw, const float* __restrict__ Qb,
    const float* __restrict__ Vw, const float* __restrict__ Vb)
{
    const int b = blockIdx.x, tid = threadIdx.x;
    __shared__ float hc_s[384];
    __shared__ float q_s[128];

    hc_s[tid]       = hN [b * E_ + tid];
    hc_s[128 + tid] = hpr[b * E_ + tid];
    hc_s[256 + tid] = h0 [b * E_ + tid];
    __syncthreads();

    {
        float a = Qb[tid];
        const float4* qr = (const float4*)(Qw + (size_t)tid * 384);
        const float4* xc = (const float4*)hc_s;
        #pragma unroll 8
        for (int i = 0; i < 96; i++) {
            float4 w = qr[i], x = xc[i];
            a += w.x * x.x + w.y * x.y + w.z * x.z + w.w * x.w;
        }
        q_s[tid] = a;
    }
    __syncthreads();

    const int k = tid;
    #pragma unroll
    for (int hh = 0; hh < 8; hh++) {
        float acc = 0.0f;
        #pragma unroll
        for (int j = 0; j < 16; j++)
            acc += q_s[hh * 16 + j] * Vw[(size_t)(hh * 16 + j) * E_ + k];
        g_u[((size_t)b * 8 + hh) * E_ + k] = 0.25f * acc;
    }
    if (tid < 8) {
        float a = 0.0f;
        #pragma unroll
        for (int j = 0; j < 16; j++)
            a += q_s[tid * 16 + j] * Vb[tid * 16 + j];
        g_qb[b * 8 + tid] = 0.25f * a;
    }
}

// ---------------------------------------------------------------------------
// K1: streaming dots + exp + weighted sums, 4 rows/iter, 128-thr CTA, occ>=3.
// ---------------------------------------------------------------------------
__global__ void __launch_bounds__(128, 3) k_fused(const float* __restrict__ h,
                                                  const int*   __restrict__ mask)
{
    const int b = blockIdx.y, part = blockIdx.x;
    const int tid = threadIdx.x, warp = tid >> 5, lane = tid & 31;

    unsigned long long u01[8], u23[8];
    #pragma unroll
    for (int hh = 0; hh < 8; hh++) {
        float4 uu = *(const float4*)&g_u[((size_t)b * 8 + hh) * E_ + lane * 4];
        u01[hh] = pk2(uu.x, uu.y);
        u23[hh] = pk2(uu.z, uu.w);
    }
    const float qbr = g_qb[b * 8 + (lane >> 2)];

    unsigned long long s2[16];          // s[h] as 2 packed pairs
    #pragma unroll
    for (int i = 0; i < 16; i++) s2[i] = pk2(0.f, 0.f);
    float l_acc = 0.0f;

    __shared__ float p_s[WPB][4][8];    // [warp][row-in-group][head]

    const float* rp = h + ((size_t)b * C_ + part * RPB + warp) * E_ + lane * 4;
    const int*   mp = mask + b * C_ + part * RPB + warp;
    const size_t rs = (size_t)WPB * E_;

    const bool hi4 = (lane & 16) != 0;
    const bool hi3 = (lane & 8)  != 0;
    const bool hi2 = (lane & 4)  != 0;

    float4 cur[4]; int mc[4];
    #pragma unroll
    for (int j = 0; j < 4; j++) {
        cur[j] = *(const float4*)(rp + (size_t)j * rs);
        mc[j]  = mp[j * WPB];
    }

    #pragma unroll 1
    for (int g = 0; g < NGRP; g++) {
        float4 nx[4]; int mn_[4];
        if (g < NGRP - 1) {
            #pragma unroll
            for (int j = 0; j < 4; j++) {
                nx[j]  = *(const float4*)(rp + (size_t)((g + 1) * 4 + j) * rs);
                mn_[j] = mp[((g + 1) * 4 + j) * WPB];
            }
        }

        unsigned long long cxy[4], czw[4];
        #pragma unroll
        for (int j = 0; j < 4; j++) {
            cxy[j] = pk2(cur[j].x, cur[j].y);
            czw[j] = pk2(cur[j].z, cur[j].w);
        }

        // packed partial dots for 4 rows x 8 heads
        float d[4][8];
        #pragma unroll
        for (int j = 0; j < 4; j++)
            #pragma unroll
            for (int hh = 0; hh < 8; hh++) {
                unsigned long long t;
                MUL2(t, cxy[j], u01[hh]);
                FMA2(t, czw[j], u23[hh]);
                float2 tt = upk2(t);
                d[j][hh] = tt.x + tt.y;
            }

        // folds, level-major (4 independent chains in flight)
        #pragma unroll
        for (int j = 0; j < 4; j++)
            #pragma unroll
            for (int t = 0; t < 4; t++) {
                float send = hi4 ? d[j][t] : d[j][t + 4];
                float keep = hi4 ? d[j][t + 4] : d[j][t];
                d[j][t] = keep + __shfl_xor_sync(0xffffffffu, send, 16);
            }
        #pragma unroll
        for (int j = 0; j < 4; j++)
            #pragma unroll
            for (int t = 0; t < 2; t++) {
                float send = hi3 ? d[j][t] : d[j][t + 2];
                float keep = hi3 ? d[j][t + 2] : d[j][t];
                d[j][t] = keep + __shfl_xor_sync(0xffffffffu, send, 8);
            }
        float dd[4];
        #pragma unroll
        for (int j = 0; j < 4; j++) {
            float send = hi2 ? d[j][0] : d[j][1];
            float keep = hi2 ? d[j][1] : d[j][0];
            dd[j] = keep + __shfl_xor_sync(0xffffffffu, send, 4);
        }
        #pragma unroll
        for (int j = 0; j < 4; j++)
            dd[j] += __shfl_xor_sync(0xffffffffu, dd[j], 2);
        #pragma unroll
        for (int j = 0; j < 4; j++)
            dd[j] += __shfl_xor_sync(0xffffffffu, dd[j], 1);

        // exp (shift-free: masked rows underflow to exact 0)
        float p[4];
        #pragma unroll
        for (int j = 0; j < 4; j++) {
            p[j] = __expf(dd[j] + qbr - (float)mc[j] * 1.0e8f);
            l_acc += p[j];
        }

        __syncwarp();
        if ((lane & 3) == 0) {
            const int k = lane >> 2;
            #pragma unroll
            for (int j = 0; j < 4; j++) p_s[warp][j][k] = p[j];
        }
        __syncwarp();

        #pragma unroll
        for (int j = 0; j < 4; j++) {
            float4 pa = *(const float4*)&p_s[warp][j][0];
            float4 pb = *(const float4*)&p_s[warp][j][4];
            unsigned long long pd;
            pd = pk2(pa.x, pa.x); FMA2(s2[0],  cxy[j], pd); FMA2(s2[1],  czw[j], pd);
            pd = pk2(pa.y, pa.y); FMA2(s2[2],  cxy[j], pd); FMA2(s2[3],  czw[j], pd);
            pd = pk2(pa.z, pa.z); FMA2(s2[4],  cxy[j], pd); FMA2(s2[5],  czw[j], pd);
            pd = pk2(pa.w, pa.w); FMA2(s2[6],  cxy[j], pd); FMA2(s2[7],  czw[j], pd);
            pd = pk2(pb.x, pb.x); FMA2(s2[8],  cxy[j], pd); FMA2(s2[9],  czw[j], pd);
            pd = pk2(pb.y, pb.y); FMA2(s2[10], cxy[j], pd); FMA2(s2[11], czw[j], pd);
            pd = pk2(pb.z, pb.z); FMA2(s2[12], cxy[j], pd); FMA2(s2[13], czw[j], pd);
            pd = pk2(pb.w, pb.w); FMA2(s2[14], cxy[j], pd); FMA2(s2[15], czw[j], pd);
        }

        #pragma unroll
        for (int j = 0; j < 4; j++) { cur[j] = nx[j]; mc[j] = mn_[j]; }
    }

    // combine WPB warps
    __shared__ float sm[WPB * 8 * 128];   // 16 KB
    __shared__ float sl[WPB][8];
    #pragma unroll
    for (int hh = 0; hh < 8; hh++) {
        float2 e01 = upk2(s2[2 * hh]);
        float2 e23 = upk2(s2[2 * hh + 1]);
        *(float4*)&sm[warp * 1024 + hh * 128 + lane * 4] =
            make_float4(e01.x, e01.y, e23.x, e23.y);
    }
    if ((lane & 3) == 0) sl[warp][lane >> 2] = l_acc;
    __syncthreads();

    const size_t base = (size_t)(b * SPLIT + part) * 8 * E_;
    #pragma unroll
    for (int k = 0; k < 8; k++) {
        int idx = tid + k * 128;
        float a = 0.0f;
        #pragma unroll
        for (int w = 0; w < WPB; w++) a += sm[w * 1024 + idx];
        g_ps[base + idx] = a;
    }
    if (tid < 8) {
        float a = 0.0f;
        #pragma unroll
        for (int w = 0; w < WPB; w++) a += sl[w][tid];
        g_pl[(b * SPLIT + part) * 8 + tid] = a;
    }
}

// ---------------------------------------------------------------------------
// K2: per batch — combine partials -> sbar -> ctx -> dec -> qf -> (w, kb)
// ---------------------------------------------------------------------------
__global__ void __launch_bounds__(128) k_epilogue(
    const float* __restrict__ Vw,  const float* __restrict__ Vb,
    const float* __restrict__ Wow, const float* __restrict__ Wob,
    const float* __restrict__ Qfw, const float* __restrict__ Qfb,
    const float* __restrict__ Kfw, const float* __restrict__ Kfb)
{
    const int b = blockIdx.x, tid = threadIdx.x;
    __shared__ float sbar[1024], ctx[128], dec[128], qf[128], r2[128];
    __shared__ float invl[8];

    if (tid < 8) {
        float L = 0.0f;
        #pragma unroll
        for (int p = 0; p < SPLIT; p++)
            L += g_pl[(b * SPLIT + p) * 8 + tid];
        invl[tid] = 1.0f / L;
    }
    __syncthreads();

    #pragma unroll
    for (int hh = 0; hh < 8; hh++) {
        float a = 0.0f;
        #pragma unroll
        for (int p = 0; p < SPLIT; p++)
            a += g_ps[(size_t)(b * SPLIT + p) * 8 * E_ + hh * E_ + tid];
        sbar[hh * 128 + tid] = a * invl[hh];
    }
    __syncthreads();

    {
        const int head = tid >> 4;
        float a = Vb[tid];
        const float4* wr = (const float4*)(Vw + (size_t)tid * E_);
        const float4* xc = (const float4*)&sbar[head * 128];
        #pragma unroll 8
        for (int i = 0; i < 32; i++) {
            float4 w = wr[i], x = xc[i];
            a += w.x * x.x + w.y * x.y + w.z * x.z + w.w * x.w;
        }
        ctx[tid] = a;
    }
    __syncthreads();
    {
        float a = Wob[tid];
        const float4* wr = (const float4*)(Wow + (size_t)tid * E_);
        const float4* xc = (const float4*)ctx;
        #pragma unroll 8
        for (int i = 0; i < 32; i++) {
            float4 w = wr[i], x = xc[i];
            a += w.x * x.x + w.y * x.y + w.z * x.z + w.w * x.w;
        }
        dec[tid] = a;
    }
    __syncthreads();
    {
        float a = Qfb[tid];
        const float4* wr = (const float4*)(Qfw + (size_t)tid * E_);
        const float4* xc = (const float4*)dec;
        #pragma unroll 8
        for (int i = 0; i < 32; i++) {
            float4 w = wr[i], x = xc[i];
            a += w.x * x.x + w.y * x.y + w.z * x.z + w.w * x.w;
        }
        qf[tid] = a;
    }
    __syncthreads();

    {
        float a = 0.0f;
        #pragma unroll 8
        for (int j = 0; j < 128; j++)
            a += qf[j] * Kfw[(size_t)j * E_ + tid];
        g_w[b * 128 + tid] = a;
    }
    r2[tid] = qf[tid] * Kfb[tid];
    __syncthreads();
    for (int st = 64; st; st >>= 1) {
        if (tid < st) r2[tid] += r2[tid + st];
        __syncthreads();
    }
    if (tid == 0) g_kb[b] = r2[0];
}

// ---------------------------------------------------------------------------
// K3: logits[b][c] = 10*tanh((h.w + kb)/sqrt(E)) - mask*1e8  (paired-row fold)
// ---------------------------------------------------------------------------
__global__ void __launch_bounds__(256) k_logits(
    const float* __restrict__ h, const int* __restrict__ mask,
    float* __restrict__ out)
{
    const int b = blockIdx.y, chunk = blockIdx.x;
    const int warp = threadIdx.x >> 5, lane = threadIdx.x & 31;

    float4 w4 = *(const float4*)&g_w[b * 128 + lane * 4];
    float  kb = g_kb[b];

    const int c0 = chunk * 256 + warp * 32;
    const float* rp = h + ((size_t)b * C_ + c0) * E_ + lane * 4;
    const bool hi = (lane & 16) != 0;
    const int  sub = lane >> 4;

    float4 a0 = *(const float4*)rp;
    float4 a1 = *(const float4*)(rp + E_);

    #pragma unroll 2
    for (int j = 0; j < 16; j++) {
        float4 r0 = a0, r1 = a1;
        if (j < 15) {
            a0 = *(const float4*)(rp + (size_t)(2 * j + 2) * E_);
            a1 = *(const float4*)(rp + (size_t)(2 * j + 3) * E_);
        }
        float p0 = r0.x * w4.x + r0.y * w4.y + r0.z * w4.z + r0.w * w4.w;
        float p1 = r1.x * w4.x + r1.y * w4.y + r1.z * w4.z + r1.w * w4.w;

        float send = hi ? p0 : p1;
        float keep = hi ? p1 : p0;
        float t = keep + __shfl_xor_sync(0xffffffffu, send, 16);
        t += __shfl_xor_sync(0xffffffffu, t, 8);
        t += __shfl_xor_sync(0xffffffffu, t, 4);
        t += __shfl_xor_sync(0xffffffffu, t, 2);
        t += __shfl_xor_sync(0xffffffffu, t, 1);

        if ((lane & 15) == 0) {
            int c = c0 + 2 * j + sub;
            float lg = (t + kb) * 0.08838834764831845f;   // 1/sqrt(128)
            out[(size_t)b * C_ + c] =
                10.0f * tanhf(lg) - (float)mask[b * C_ + c] * 1.0e8f;
        }
    }
}

// ---------------------------------------------------------------------------
extern "C" void kernel_launch(void* const* d_in, const int* in_sizes, int n_in,
                              void* d_out, int out_size) {
    const float* h    = (const float*)d_in[0];
    const float* hN   = (const float*)d_in[1];
    const float* hpr  = (const float*)d_in[2];
    const float* h0   = (const float*)d_in[3];
    const int*   mask = (const int*)  d_in[4];
    const float* Qw   = (const float*)d_in[5];
    const float* Qb   = (const float*)d_in[6];
    const float* Vw   = (const float*)d_in[7];
    const float* Vb   = (const float*)d_in[8];
    const float* Wow  = (const float*)d_in[9];
    const float* Wob  = (const float*)d_in[10];
    const float* Qfw  = (const float*)d_in[11];
    const float* Qfb  = (const float*)d_in[12];
    const float* Kfw  = (const float*)d_in[13];
    const float* Kfb  = (const float*)d_in[14];
    float* out = (float*)d_out;

    k_prep    <<<B_, 128>>>(hN, hpr, h0, Qw, Qb, Vw, Vb);
    k_fused   <<<dim3(SPLIT, B_), 128>>>(h, mask);
    k_epilogue<<<B_, 128>>>(Vw, Vb, Wow, Wob, Qfw, Qfb, Kfw, Kfb);
    k_logits  <<<dim3(4, B_), 256>>>(h, mask, out);
}

// round 9
// speedup vs baseline: 1.2905x; 1.2905x over previous
#include <cuda_runtime.h>
#include <math.h>

#define B_    1024
#define C_    1024
#define E_    128
#define SPLIT 4
#define RPB   (C_ / SPLIT)    // 256 rows per fused block
#define NGRP  16              // 16 groups of 4 rows per stream (64 rows/stream)

// ---------------- device scratch (allocation-free rule) ----------------
__device__ float g_u [B_ * 8 * E_];          // per-batch per-head score vectors (0.25 folded)
__device__ float g_qb[B_ * 8];               // per-head score bias (0.25 folded)
__device__ float g_pl[B_ * SPLIT * 8];       // partial sum-exp
__device__ float g_ps[(size_t)B_ * SPLIT * 8 * E_];  // partial weighted h sums
__device__ float g_w [B_ * E_];              // logits matvec vector
__device__ float g_kb[B_];                   // logits scalar bias

// ---------------- f32x2 helpers (sm_103 packed fp32) ----------------
__device__ __forceinline__ unsigned long long pk2(float x, float y) {
    unsigned long long r;
    asm("mov.b64 %0, {%1, %2};" : "=l"(r) : "f"(x), "f"(y));
    return r;
}
__device__ __forceinline__ float2 upk2(unsigned long long v) {
    float2 r;
    asm("mov.b64 {%0, %1}, %2;" : "=f"(r.x), "=f"(r.y) : "l"(v));
    return r;
}
#define MUL2(d, a, b) asm("mul.rn.f32x2 %0, %1, %2;" : "=l"(d) : "l"(a), "l"(b))
#define FMA2(d, a, b) asm("fma.rn.f32x2 %0, %1, %2, %0;" : "+l"(d) : "l"(a), "l"(b))

// ---------------------------------------------------------------------------
// K0: per batch — q = Qw@hc + Qb;  u[h][:] = 0.25 * q_h^T Vw_h ;  qb[h] = 0.25 q_h.Vb_h
// ---------------------------------------------------------------------------
__global__ void __launch_bounds__(128) k_prep(
    const float* __restrict__ hN, const float* __restrict__ hpr,
    const float* __restrict__ h0,
    const float* __restrict__ Qw, const float* __restrict__ Qb,
    const float* __restrict__ Vw, const float* __restrict__ Vb)
{
    const int b = blockIdx.x, tid = threadIdx.x;
    __shared__ float hc_s[384];
    __shared__ float q_s[128];

    hc_s[tid]       = hN [b * E_ + tid];
    hc_s[128 + tid] = hpr[b * E_ + tid];
    hc_s[256 + tid] = h0 [b * E_ + tid];
    __syncthreads();

    {
        float a = Qb[tid];
        const float4* qr = (const float4*)(Qw + (size_t)tid * 384);
        const float4* xc = (const float4*)hc_s;
        #pragma unroll 8
        for (int i = 0; i < 96; i++) {
            float4 w = qr[i], x = xc[i];
            a += w.x * x.x + w.y * x.y + w.z * x.z + w.w * x.w;
        }
        q_s[tid] = a;
    }
    __syncthreads();

    const int k = tid;
    #pragma unroll
    for (int hh = 0; hh < 8; hh++) {
        float acc = 0.0f;
        #pragma unroll
        for (int j = 0; j < 16; j++)
            acc += q_s[hh * 16 + j] * Vw[(size_t)(hh * 16 + j) * E_ + k];
        g_u[((size_t)b * 8 + hh) * E_ + k] = 0.25f * acc;
    }
    if (tid < 8) {
        float a = 0.0f;
        #pragma unroll
        for (int j = 0; j < 16; j++)
            a += q_s[tid * 16 + j] * Vb[tid * 16 + j];
        g_qb[b * 8 + tid] = 0.25f * a;
    }
}

// ---------------------------------------------------------------------------
// K1: streaming dots + exp + weighted sums.
//     Warp pairs: warp w & w+4 stream the same rows; each handles 4 heads.
// ---------------------------------------------------------------------------
__global__ void __launch_bounds__(256, 2) k_fused(const float* __restrict__ h,
                                                  const int*   __restrict__ mask)
{
    const int b = blockIdx.y, part = blockIdx.x;
    const int tid = threadIdx.x, warp = tid >> 5, lane = tid & 31;
    const int hg = warp >> 2;       // head group: heads hg*4 .. hg*4+3
    const int ws = warp & 3;        // row stream 0..3

    // u for this warp's 4 heads (lane owns e = lane*4..+3)
    unsigned long long u01[4], u23[4];
    #pragma unroll
    for (int hh = 0; hh < 4; hh++) {
        float4 uu = *(const float4*)&g_u[((size_t)b * 8 + hg * 4 + hh) * E_ + lane * 4];
        u01[hh] = pk2(uu.x, uu.y);
        u23[hh] = pk2(uu.z, uu.w);
    }
    const float qbr = g_qb[b * 8 + hg * 4 + (lane >> 3)];

    unsigned long long s2[8];       // 4 heads x 2 packed pairs
    #pragma unroll
    for (int i = 0; i < 8; i++) s2[i] = pk2(0.f, 0.f);
    float l_acc = 0.0f;

    __shared__ float p_s[8][4][4];  // [warp][row-in-group][head-in-group]

    // stream ws covers rows part*RPB + ws + 4*i  (i = 0..63)
    const float* rp = h + ((size_t)b * C_ + part * RPB + ws) * E_ + lane * 4;
    const int*   mp = mask + b * C_ + part * RPB + ws;
    const size_t rs = (size_t)4 * E_;

    const bool hi4 = (lane & 16) != 0;
    const bool hi3 = (lane & 8)  != 0;

    float4 cur[4]; int mc[4];
    #pragma unroll
    for (int j = 0; j < 4; j++) {
        cur[j] = *(const float4*)(rp + (size_t)j * rs);
        mc[j]  = mp[j * 4];
    }

    #pragma unroll 1
    for (int g = 0; g < NGRP; g++) {
        float4 nx[4]; int mn_[4];
        if (g < NGRP - 1) {
            #pragma unroll
            for (int j = 0; j < 4; j++) {
                nx[j]  = *(const float4*)(rp + (size_t)((g + 1) * 4 + j) * rs);
                mn_[j] = mp[((g + 1) * 4 + j) * 4];
            }
        }

        // packed partial dots: 4 rows x 4 heads
        float d[4][4];
        #pragma unroll
        for (int j = 0; j < 4; j++) {
            unsigned long long cxy = pk2(cur[j].x, cur[j].y);
            unsigned long long czw = pk2(cur[j].z, cur[j].w);
            #pragma unroll
            for (int hh = 0; hh < 4; hh++) {
                unsigned long long t;
                MUL2(t, cxy, u01[hh]);
                FMA2(t, czw, u23[hh]);
                float2 tt = upk2(t);
                d[j][hh] = tt.x + tt.y;
            }
        }

        // head-folding (4 heads -> lane>>3), level-major across 4 rows: 6 shfl/row
        #pragma unroll
        for (int j = 0; j < 4; j++)
            #pragma unroll
            for (int t = 0; t < 2; t++) {
                float send = hi4 ? d[j][t] : d[j][t + 2];
                float keep = hi4 ? d[j][t + 2] : d[j][t];
                d[j][t] = keep + __shfl_xor_sync(0xffffffffu, send, 16);
            }
        float dd[4];
        #pragma unroll
        for (int j = 0; j < 4; j++) {
            float send = hi3 ? d[j][0] : d[j][1];
            float keep = hi3 ? d[j][1] : d[j][0];
            dd[j] = keep + __shfl_xor_sync(0xffffffffu, send, 8);
        }
        #pragma unroll
        for (int j = 0; j < 4; j++)
            dd[j] += __shfl_xor_sync(0xffffffffu, dd[j], 4);
        #pragma unroll
        for (int j = 0; j < 4; j++)
            dd[j] += __shfl_xor_sync(0xffffffffu, dd[j], 2);
        #pragma unroll
        for (int j = 0; j < 4; j++)
            dd[j] += __shfl_xor_sync(0xffffffffu, dd[j], 1);

        // exp (shift-free: masked rows underflow to exact 0)
        float p[4];
        #pragma unroll
        for (int j = 0; j < 4; j++) {
            p[j] = __expf(dd[j] + qbr - (float)mc[j] * 1.0e8f);
            l_acc += p[j];
        }

        __syncwarp();
        if ((lane & 7) == 0) {
            const int k = lane >> 3;
            #pragma unroll
            for (int j = 0; j < 4; j++) p_s[warp][j][k] = p[j];
        }
        __syncwarp();

        // accumulate weighted sums: 8 FMA2 per row
        #pragma unroll
        for (int j = 0; j < 4; j++) {
            float4 pq = *(const float4*)&p_s[warp][j][0];
            unsigned long long cxy = pk2(cur[j].x, cur[j].y);
            unsigned long long czw = pk2(cur[j].z, cur[j].w);
            unsigned long long pd;
            pd = pk2(pq.x, pq.x); FMA2(s2[0], cxy, pd); FMA2(s2[1], czw, pd);
            pd = pk2(pq.y, pq.y); FMA2(s2[2], cxy, pd); FMA2(s2[3], czw, pd);
            pd = pk2(pq.z, pq.z); FMA2(s2[4], cxy, pd); FMA2(s2[5], czw, pd);
            pd = pk2(pq.w, pq.w); FMA2(s2[6], cxy, pd); FMA2(s2[7], czw, pd);
        }

        #pragma unroll
        for (int j = 0; j < 4; j++) { cur[j] = nx[j]; mc[j] = mn_[j]; }
    }

    // combine: head h<4 from warps 0-3, h>=4 from warps 4-7
    __shared__ float sm[8 * 4 * 128];     // [warp][head-in-group][e] = 16 KB
    __shared__ float sl[8][4];
    #pragma unroll
    for (int hh = 0; hh < 4; hh++) {
        float2 e01 = upk2(s2[2 * hh]);
        float2 e23 = upk2(s2[2 * hh + 1]);
        *(float4*)&sm[warp * 512 + hh * 128 + lane * 4] =
            make_float4(e01.x, e01.y, e23.x, e23.y);
    }
    if ((lane & 7) == 0) sl[warp][lane >> 3] = l_acc;
    __syncthreads();

    const size_t base = (size_t)(b * SPLIT + part) * 8 * E_;
    #pragma unroll
    for (int k = 0; k < 4; k++) {
        int idx = tid + k * 256;          // 0..1023 -> (h, e)
        int hh = idx >> 7, e = idx & 127;
        int w0 = (hh >> 2) * 4, hi = hh & 3;
        float a = 0.0f;
        #pragma unroll
        for (int w = 0; w < 4; w++) a += sm[(w0 + w) * 512 + hi * 128 + e];
        g_ps[base + idx] = a;
    }
    if (tid < 8) {
        int w0 = (tid >> 2) * 4, hi = tid & 3;
        float a = 0.0f;
        #pragma unroll
        for (int w = 0; w < 4; w++) a += sl[w0 + w][hi];
        g_pl[(b * SPLIT + part) * 8 + tid] = a;
    }
}

// ---------------------------------------------------------------------------
// K2: per batch — combine partials -> sbar -> ctx -> dec -> qf -> (w, kb)
// ---------------------------------------------------------------------------
__global__ void __launch_bounds__(128) k_epilogue(
    const float* __restrict__ Vw,  const float* __restrict__ Vb,
    const float* __restrict__ Wow, const float* __restrict__ Wob,
    const float* __restrict__ Qfw, const float* __restrict__ Qfb,
    const float* __restrict__ Kfw, const float* __restrict__ Kfb)
{
    const int b = blockIdx.x, tid = threadIdx.x;
    __shared__ float sbar[1024], ctx[128], dec[128], qf[128], r2[128];
    __shared__ float invl[8];

    if (tid < 8) {
        float L = 0.0f;
        #pragma unroll
        for (int p = 0; p < SPLIT; p++)
            L += g_pl[(b * SPLIT + p) * 8 + tid];
        invl[tid] = 1.0f / L;
    }
    __syncthreads();

    #pragma unroll
    for (int hh = 0; hh < 8; hh++) {
        float a = 0.0f;
        #pragma unroll
        for (int p = 0; p < SPLIT; p++)
            a += g_ps[(size_t)(b * SPLIT + p) * 8 * E_ + hh * E_ + tid];
        sbar[hh * 128 + tid] = a * invl[hh];
    }
    __syncthreads();

    {
        const int head = tid >> 4;
        float a = Vb[tid];
        const float4* wr = (const float4*)(Vw + (size_t)tid * E_);
        const float4* xc = (const float4*)&sbar[head * 128];
        #pragma unroll 8
        for (int i = 0; i < 32; i++) {
            float4 w = wr[i], x = xc[i];
            a += w.x * x.x + w.y * x.y + w.z * x.z + w.w * x.w;
        }
        ctx[tid] = a;
    }
    __syncthreads();
    {
        float a = Wob[tid];
        const float4* wr = (const float4*)(Wow + (size_t)tid * E_);
        const float4* xc = (const float4*)ctx;
        #pragma unroll 8
        for (int i = 0; i < 32; i++) {
            float4 w = wr[i], x = xc[i];
            a += w.x * x.x + w.y * x.y + w.z * x.z + w.w * x.w;
        }
        dec[tid] = a;
    }
    __syncthreads();
    {
        float a = Qfb[tid];
        const float4* wr = (const float4*)(Qfw + (size_t)tid * E_);
        const float4* xc = (const float4*)dec;
        #pragma unroll 8
        for (int i = 0; i < 32; i++) {
            float4 w = wr[i], x = xc[i];
            a += w.x * x.x + w.y * x.y + w.z * x.z + w.w * x.w;
        }
        qf[tid] = a;
    }
    __syncthreads();

    {
        float a = 0.0f;
        #pragma unroll 8
        for (int j = 0; j < 128; j++)
            a += qf[j] * Kfw[(size_t)j * E_ + tid];
        g_w[b * 128 + tid] = a;
    }
    r2[tid] = qf[tid] * Kfb[tid];
    __syncthreads();
    for (int st = 64; st; st >>= 1) {
        if (tid < st) r2[tid] += r2[tid + st];
        __syncthreads();
    }
    if (tid == 0) g_kb[b] = r2[0];
}

// ---------------------------------------------------------------------------
// K3: logits[b][c] = 10*tanh((h.w + kb)/sqrt(E)) - mask*1e8  (paired-row fold)
// ---------------------------------------------------------------------------
__global__ void __launch_bounds__(256) k_logits(
    const float* __restrict__ h, const int* __restrict__ mask,
    float* __restrict__ out)
{
    const int b = blockIdx.y, chunk = blockIdx.x;
    const int warp = threadIdx.x >> 5, lane = threadIdx.x & 31;

    float4 w4 = *(const float4*)&g_w[b * 128 + lane * 4];
    float  kb = g_kb[b];

    const int c0 = chunk * 256 + warp * 32;
    const float* rp = h + ((size_t)b * C_ + c0) * E_ + lane * 4;
    const bool hi = (lane & 16) != 0;
    const int  sub = lane >> 4;

    float4 a0 = *(const float4*)rp;
    float4 a1 = *(const float4*)(rp + E_);

    #pragma unroll 2
    for (int j = 0; j < 16; j++) {
        float4 r0 = a0, r1 = a1;
        if (j < 15) {
            a0 = *(const float4*)(rp + (size_t)(2 * j + 2) * E_);
            a1 = *(const float4*)(rp + (size_t)(2 * j + 3) * E_);
        }
        float p0 = r0.x * w4.x + r0.y * w4.y + r0.z * w4.z + r0.w * w4.w;
        float p1 = r1.x * w4.x + r1.y * w4.y + r1.z * w4.z + r1.w * w4.w;

        float send = hi ? p0 : p1;
        float keep = hi ? p1 : p0;
        float t = keep + __shfl_xor_sync(0xffffffffu, send, 16);
        t += __shfl_xor_sync(0xffffffffu, t, 8);
        t += __shfl_xor_sync(0xffffffffu, t, 4);
        t += __shfl_xor_sync(0xffffffffu, t, 2);
        t += __shfl_xor_sync(0xffffffffu, t, 1);

        if ((lane & 15) == 0) {
            int c = c0 + 2 * j + sub;
            float lg = (t + kb) * 0.08838834764831845f;   // 1/sqrt(128)
            out[(size_t)b * C_ + c] =
                10.0f * tanhf(lg) - (float)mask[b * C_ + c] * 1.0e8f;
        }
    }
}

// ---------------------------------------------------------------------------
extern "C" void kernel_launch(void* const* d_in, const int* in_sizes, int n_in,
                              void* d_out, int out_size) {
    const float* h    = (const float*)d_in[0];
    const float* hN   = (const float*)d_in[1];
    const float* hpr  = (const float*)d_in[2];
    const float* h0   = (const float*)d_in[3];
    const int*   mask = (const int*)  d_in[4];
    const float* Qw   = (const float*)d_in[5];
    const float* Qb   = (const float*)d_in[6];
    const float* Vw   = (const float*)d_in[7];
    const float* Vb   = (const float*)d_in[8];
    const float* Wow  = (const float*)d_in[9];
    const float* Wob  = (const float*)d_in[10];
    const float* Qfw  = (const float*)d_in[11];
    const float* Qfb  = (const float*)d_in[12];
    const float* Kfw  = (const float*)d_in[13];
    const float* Kfb  = (const float*)d_in[14];
    float* out = (float*)d_out;

    k_prep    <<<B_, 128>>>(hN, hpr, h0, Qw, Qb, Vw, Vb);
    k_fused   <<<dim3(SPLIT, B_), 256>>>(h, mask);
    k_epilogue<<<B_, 128>>>(Vw, Vb, Wow, Wob, Qfw, Qfb, Kfw, Kfb);
    k_logits  <<<dim3(4, B_), 256>>>(h, mask, out);
}

// round 11
// speedup vs baseline: 1.4266x; 1.1055x over previous
#include <cuda_runtime.h>
#include <math.h>
#include <stdint.h>

#define B_    1024
#define C_    1024
#define E_    128
#define SPLIT 4
#define RPB   (C_ / SPLIT)    // 256 rows per fused block
#define TROWS 64              // rows per pipeline stage (32KB)
#define NT    (RPB / TROWS)   // 4 stages
#define NGRP  4               // groups of 4 rows per warp-stream per stage

// ---------------- device scratch (allocation-free rule) ----------------
__device__ float g_u [B_ * 8 * E_];
__device__ float g_qb[B_ * 8];
__device__ float g_pl[B_ * SPLIT * 8];
__device__ float g_ps[(size_t)B_ * SPLIT * 8 * E_];
__device__ float g_w [B_ * E_];
__device__ float g_kb[B_];

// ---------------- f32x2 helpers ----------------
__device__ __forceinline__ unsigned long long pk2(float x, float y) {
    unsigned long long r;
    asm("mov.b64 %0, {%1, %2};" : "=l"(r) : "f"(x), "f"(y));
    return r;
}
__device__ __forceinline__ float2 upk2(unsigned long long v) {
    float2 r;
    asm("mov.b64 {%0, %1}, %2;" : "=f"(r.x), "=f"(r.y) : "l"(v));
    return r;
}
#define MUL2(d, a, b) asm("mul.rn.f32x2 %0, %1, %2;" : "=l"(d) : "l"(a), "l"(b))
#define FMA2(d, a, b) asm("fma.rn.f32x2 %0, %1, %2, %0;" : "+l"(d) : "l"(a), "l"(b))

__device__ __forceinline__ void cp16(unsigned int dst, const void* src) {
    asm volatile("cp.async.cg.shared.global [%0], [%1], 16;" :: "r"(dst), "l"(src));
}

// ---------------------------------------------------------------------------
// K0: per batch — q = Qw@hc + Qb;  u[h][:] = 0.25 q_h^T Vw_h;  qb[h] = 0.25 q_h.Vb_h
// ---------------------------------------------------------------------------
__global__ void __launch_bounds__(128) k_prep(
    const float* __restrict__ hN, const float* __restrict__ hpr,
    const float* __restrict__ h0,
    const float* __restrict__ Qw, const float* __restrict__ Qb,
    const float* __restrict__ Vw, const float* __restrict__ Vb)
{
    const int b = blockIdx.x, tid = threadIdx.x;
    __shared__ float hc_s[384];
    __shared__ float q_s[128];

    hc_s[tid]       = hN [b * E_ + tid];
    hc_s[128 + tid] = hpr[b * E_ + tid];
    hc_s[256 + tid] = h0 [b * E_ + tid];
    __syncthreads();

    {
        float a = Qb[tid];
        const float4* qr = (const float4*)(Qw + (size_t)tid * 384);
        const float4* xc = (const float4*)hc_s;
        #pragma unroll 8
        for (int i = 0; i < 96; i++) {
            float4 w = qr[i], x = xc[i];
            a += w.x * x.x + w.y * x.y + w.z * x.z + w.w * x.w;
        }
        q_s[tid] = a;
    }
    __syncthreads();

    const int k = tid;
    #pragma unroll
    for (int hh = 0; hh < 8; hh++) {
        float acc = 0.0f;
        #pragma unroll
        for (int j = 0; j < 16; j++)
            acc += q_s[hh * 16 + j] * Vw[(size_t)(hh * 16 + j) * E_ + k];
        g_u[((size_t)b * 8 + hh) * E_ + k] = 0.25f * acc;
    }
    if (tid < 8) {
        float a = 0.0f;
        #pragma unroll
        for (int j = 0; j < 16; j++)
            a += q_s[tid * 16 + j] * Vb[tid * 16 + j];
        g_qb[b * 8 + tid] = 0.25f * a;
    }
}

// ---------------------------------------------------------------------------
// K1: cp.async double-buffered h tiles; warp-pair heads; dots+exp+wsum from smem.
// ---------------------------------------------------------------------------
__global__ void __launch_bounds__(256, 2) k_fused(const float* __restrict__ h,
                                                  const int*   __restrict__ mask)
{
    const int b = blockIdx.y, part = blockIdx.x;
    const int tid = threadIdx.x, warp = tid >> 5, lane = tid & 31;
    const int hg = warp >> 2;       // head group: heads hg*4 .. hg*4+3
    const int ws = warp & 3;        // row stream within tile

    extern __shared__ float hbuf[];            // 2 stages x 8192 floats (64KB)
    __shared__ int   mask_s[2][TROWS];
    __shared__ float p_s[8][4][4];

    const float* hb = h + ((size_t)b * C_ + part * RPB) * E_;
    const int*   mb = mask + b * C_ + part * RPB;

    // ---- stage loader: 256 threads x 8 x 16B = 32KB, + 256B mask ----
    auto load_stage = [&](int t) {
        float* dst = hbuf + (t & 1) * 8192;
        const float* src = hb + (size_t)t * TROWS * E_;
        unsigned int d0 = (unsigned int)__cvta_generic_to_shared(dst + tid * 4);
        #pragma unroll
        for (int k = 0; k < 8; k++)
            cp16(d0 + k * 4096, src + k * 1024 + tid * 4);
        if (tid < 16) {
            unsigned int dm = (unsigned int)__cvta_generic_to_shared(&mask_s[t & 1][tid * 4]);
            cp16(dm, mb + t * TROWS + tid * 4);
        }
    };

    load_stage(0);
    asm volatile("cp.async.commit_group;");
    load_stage(1);
    asm volatile("cp.async.commit_group;");

    // u for this warp's 4 heads
    unsigned long long u01[4], u23[4];
    #pragma unroll
    for (int hh = 0; hh < 4; hh++) {
        float4 uu = *(const float4*)&g_u[((size_t)b * 8 + hg * 4 + hh) * E_ + lane * 4];
        u01[hh] = pk2(uu.x, uu.y);
        u23[hh] = pk2(uu.z, uu.w);
    }
    const float qbr = g_qb[b * 8 + hg * 4 + (lane >> 3)];

    unsigned long long s2[8];
    #pragma unroll
    for (int i = 0; i < 8; i++) s2[i] = pk2(0.f, 0.f);
    float l_acc = 0.0f;

    const bool hi4 = (lane & 16) != 0;
    const bool hi3 = (lane & 8)  != 0;

    #pragma unroll 1
    for (int t = 0; t < NT; t++) {
        if (t == NT - 1) asm volatile("cp.async.wait_group 0;");
        else             asm volatile("cp.async.wait_group 1;");
        __syncthreads();

        const float* hs = hbuf + (t & 1) * 8192;
        const int*   ms = mask_s[t & 1];

        #pragma unroll 1
        for (int g = 0; g < NGRP; g++) {
            // rows r_j = ws + 16g + 4j
            float4 cur[4]; int mc[4];
            #pragma unroll
            for (int j = 0; j < 4; j++) {
                int r = ws + 16 * g + 4 * j;
                cur[j] = *(const float4*)&hs[r * 128 + lane * 4];
                mc[j]  = ms[r];
            }

            // packed partial dots: 4 rows x 4 heads
            float d[4][4];
            #pragma unroll
            for (int j = 0; j < 4; j++) {
                unsigned long long cxy = pk2(cur[j].x, cur[j].y);
                unsigned long long czw = pk2(cur[j].z, cur[j].w);
                #pragma unroll
                for (int hh = 0; hh < 4; hh++) {
                    unsigned long long tt;
                    MUL2(tt, cxy, u01[hh]);
                    FMA2(tt, czw, u23[hh]);
                    float2 t2 = upk2(tt);
                    d[j][hh] = t2.x + t2.y;
                }
            }

            // head folding (4 heads -> lane>>3), level-major
            #pragma unroll
            for (int j = 0; j < 4; j++)
                #pragma unroll
                for (int q = 0; q < 2; q++) {
                    float send = hi4 ? d[j][q] : d[j][q + 2];
                    float keep = hi4 ? d[j][q + 2] : d[j][q];
                    d[j][q] = keep + __shfl_xor_sync(0xffffffffu, send, 16);
                }
            float dd[4];
            #pragma unroll
            for (int j = 0; j < 4; j++) {
                float send = hi3 ? d[j][0] : d[j][1];
                float keep = hi3 ? d[j][1] : d[j][0];
                dd[j] = keep + __shfl_xor_sync(0xffffffffu, send, 8);
            }
            #pragma unroll
            for (int j = 0; j < 4; j++)
                dd[j] += __shfl_xor_sync(0xffffffffu, dd[j], 4);
            #pragma unroll
            for (int j = 0; j < 4; j++)
                dd[j] += __shfl_xor_sync(0xffffffffu, dd[j], 2);
            #pragma unroll
            for (int j = 0; j < 4; j++)
                dd[j] += __shfl_xor_sync(0xffffffffu, dd[j], 1);

            float p[4];
            #pragma unroll
            for (int j = 0; j < 4; j++) {
                p[j] = __expf(dd[j] + qbr - (float)mc[j] * 1.0e8f);
                l_acc += p[j];
            }

            __syncwarp();
            if ((lane & 7) == 0) {
                const int k = lane >> 3;
                #pragma unroll
                for (int j = 0; j < 4; j++) p_s[warp][j][k] = p[j];
            }
            __syncwarp();

            #pragma unroll
            for (int j = 0; j < 4; j++) {
                float4 pq = *(const float4*)&p_s[warp][j][0];
                unsigned long long cxy = pk2(cur[j].x, cur[j].y);
                unsigned long long czw = pk2(cur[j].z, cur[j].w);
                unsigned long long pd;
                pd = pk2(pq.x, pq.x); FMA2(s2[0], cxy, pd); FMA2(s2[1], czw, pd);
                pd = pk2(pq.y, pq.y); FMA2(s2[2], cxy, pd); FMA2(s2[3], czw, pd);
                pd = pk2(pq.z, pq.z); FMA2(s2[4], cxy, pd); FMA2(s2[5], czw, pd);
                pd = pk2(pq.w, pq.w); FMA2(s2[6], cxy, pd); FMA2(s2[7], czw, pd);
            }
        }

        __syncthreads();                 // all reads of this stage done
        if (t + 2 < NT) {
            load_stage(t + 2);
            asm volatile("cp.async.commit_group;");
        }
    }

    // combine: heads h<4 from warps 0-3, h>=4 from warps 4-7
    __shared__ float sm[8 * 4 * 128];    // 16 KB
    __shared__ float sl[8][4];
    #pragma unroll
    for (int hh = 0; hh < 4; hh++) {
        float2 e01 = upk2(s2[2 * hh]);
        float2 e23 = upk2(s2[2 * hh + 1]);
        *(float4*)&sm[warp * 512 + hh * 128 + lane * 4] =
            make_float4(e01.x, e01.y, e23.x, e23.y);
    }
    if ((lane & 7) == 0) sl[warp][lane >> 3] = l_acc;
    __syncthreads();

    const size_t base = (size_t)(b * SPLIT + part) * 8 * E_;
    #pragma unroll
    for (int k = 0; k < 4; k++) {
        int idx = tid + k * 256;
        int hh = idx >> 7, e = idx & 127;
        int w0 = (hh >> 2) * 4, hi = hh & 3;
        float a = 0.0f;
        #pragma unroll
        for (int w = 0; w < 4; w++) a += sm[(w0 + w) * 512 + hi * 128 + e];
        g_ps[base + idx] = a;
    }
    if (tid < 8) {
        int w0 = (tid >> 2) * 4, hi = tid & 3;
        float a = 0.0f;
        #pragma unroll
        for (int w = 0; w < 4; w++) a += sl[w0 + w][hi];
        g_pl[(b * SPLIT + part) * 8 + tid] = a;
    }
}

// ---------------------------------------------------------------------------
// K2: per batch — combine partials -> sbar -> ctx -> dec -> qf -> (w, kb)
// ---------------------------------------------------------------------------
__global__ void __launch_bounds__(128) k_epilogue(
    const float* __restrict__ Vw,  const float* __restrict__ Vb,
    const float* __restrict__ Wow, const float* __restrict__ Wob,
    const float* __restrict__ Qfw, const float* __restrict__ Qfb,
    const float* __restrict__ Kfw, const float* __restrict__ Kfb)
{
    const int b = blockIdx.x, tid = threadIdx.x;
    __shared__ float sbar[1024], ctx[128], dec[128], qf[128], r2[128];
    __shared__ float invl[8];

    if (tid < 8) {
        float L = 0.0f;
        #pragma unroll
        for (int p = 0; p < SPLIT; p++)
            L += g_pl[(b * SPLIT + p) * 8 + tid];
        invl[tid] = 1.0f / L;
    }
    __syncthreads();

    #pragma unroll
    for (int hh = 0; hh < 8; hh++) {
        float a = 0.0f;
        #pragma unroll
        for (int p = 0; p < SPLIT; p++)
            a += g_ps[(size_t)(b * SPLIT + p) * 8 * E_ + hh * E_ + tid];
        sbar[hh * 128 + tid] = a * invl[hh];
    }
    __syncthreads();

    {
        const int head = tid >> 4;
        float a = Vb[tid];
        const float4* wr = (const float4*)(Vw + (size_t)tid * E_);
        const float4* xc = (const float4*)&sbar[head * 128];
        #pragma unroll 8
        for (int i = 0; i < 32; i++) {
            float4 w = wr[i], x = xc[i];
            a += w.x * x.x + w.y * x.y + w.z * x.z + w.w * x.w;
        }
        ctx[tid] = a;
    }
    __syncthreads();
    {
        float a = Wob[tid];
        const float4* wr = (const float4*)(Wow + (size_t)tid * E_);
        const float4* xc = (const float4*)ctx;
        #pragma unroll 8
        for (int i = 0; i < 32; i++) {
            float4 w = wr[i], x = xc[i];
            a += w.x * x.x + w.y * x.y + w.z * x.z + w.w * x.w;
        }
        dec[tid] = a;
    }
    __syncthreads();
    {
        float a = Qfb[tid];
        const float4* wr = (const float4*)(Qfw + (size_t)tid * E_);
        const float4* xc = (const float4*)dec;
        #pragma unroll 8
        for (int i = 0; i < 32; i++) {
            float4 w = wr[i], x = xc[i];
            a += w.x * x.x + w.y * x.y + w.z * x.z + w.w * x.w;
        }
        qf[tid] = a;
    }
    __syncthreads();

    {
        float a = 0.0f;
        #pragma unroll 8
        for (int j = 0; j < 128; j++)
            a += qf[j] * Kfw[(size_t)j * E_ + tid];
        g_w[b * 128 + tid] = a;
    }
    r2[tid] = qf[tid] * Kfb[tid];
    __syncthreads();
    for (int st = 64; st; st >>= 1) {
        if (tid < st) r2[tid] += r2[tid + st];
        __syncthreads();
    }
    if (tid == 0) g_kb[b] = r2[0];
}

// ---------------------------------------------------------------------------
// K3: logits[b][c] = 10*tanh((h.w + kb)/sqrt(E)) - mask*1e8  (paired-row fold)
// ---------------------------------------------------------------------------
__global__ void __launch_bounds__(256) k_logits(
    const float* __restrict__ h, const int* __restrict__ mask,
    float* __restrict__ out)
{
    const int b = blockIdx.y, chunk = blockIdx.x;
    const int warp = threadIdx.x >> 5, lane = threadIdx.x & 31;

    float4 w4 = *(const float4*)&g_w[b * 128 + lane * 4];
    float  kb = g_kb[b];

    const int c0 = chunk * 256 + warp * 32;
    const float* rp = h + ((size_t)b * C_ + c0) * E_ + lane * 4;
    const bool hi = (lane & 16) != 0;
    const int  sub = lane >> 4;

    float4 a0 = *(const float4*)rp;
    float4 a1 = *(const float4*)(rp + E_);

    #pragma unroll 2
    for (int j = 0; j < 16; j++) {
        float4 r0 = a0, r1 = a1;
        if (j < 15) {
            a0 = *(const float4*)(rp + (size_t)(2 * j + 2) * E_);
            a1 = *(const float4*)(rp + (size_t)(2 * j + 3) * E_);
        }
        float p0 = r0.x * w4.x + r0.y * w4.y + r0.z * w4.z + r0.w * w4.w;
        float p1 = r1.x * w4.x + r1.y * w4.y + r1.z * w4.z + r1.w * w4.w;

        float send = hi ? p0 : p1;
        float keep = hi ? p1 : p0;
        float t = keep + __shfl_xor_sync(0xffffffffu, send, 16);
        t += __shfl_xor_sync(0xffffffffu, t, 8);
        t += __shfl_xor_sync(0xffffffffu, t, 4);
        t += __shfl_xor_sync(0xffffffffu, t, 2);
        t += __shfl_xor_sync(0xffffffffu, t, 1);

        if ((lane & 15) == 0) {
            int c = c0 + 2 * j + sub;
            float lg = (t + kb) * 0.08838834764831845f;
            out[(size_t)b * C_ + c] =
                10.0f * tanhf(lg) - (float)mask[b * C_ + c] * 1.0e8f;
        }
    }
}

// ---------------------------------------------------------------------------
extern "C" void kernel_launch(void* const* d_in, const int* in_sizes, int n_in,
                              void* d_out, int out_size) {
    const float* h    = (const float*)d_in[0];
    const float* hN   = (const float*)d_in[1];
    const float* hpr  = (const float*)d_in[2];
    const float* h0   = (const float*)d_in[3];
    const int*   mask = (const int*)  d_in[4];
    const float* Qw   = (const float*)d_in[5];
    const float* Qb   = (const float*)d_in[6];
    const float* Vw   = (const float*)d_in[7];
    const float* Vb   = (const float*)d_in[8];
    const float* Wow  = (const float*)d_in[9];
    const float* Wob  = (const float*)d_in[10];
    const float* Qfw  = (const float*)d_in[11];
    const float* Qfb  = (const float*)d_in[12];
    const float* Kfw  = (const float*)d_in[13];
    const float* Kfb  = (const float*)d_in[14];
    float* out = (float*)d_out;

    const int DSMEM = 2 * TROWS * E_ * (int)sizeof(float);   // 64 KB
    cudaFuncSetAttribute(k_fused, cudaFuncAttributeMaxDynamicSharedMemorySize, DSMEM);

    k_prep    <<<B_, 128>>>(hN, hpr, h0, Qw, Qb, Vw, Vb);
    k_fused   <<<dim3(SPLIT, B_), 256, DSMEM>>>(h, mask);
    k_epilogue<<<B_, 128>>>(Vw, Vb, Wow, Wob, Qfw, Qfb, Kfw, Kfb);
    k_logits  <<<dim3(4, B_), 256>>>(h, mask, out);
}